// round 10
// baseline (speedup 1.0000x reference)
#include <cuda_runtime.h>
#include <cuda_fp16.h>
#include <cstdint>

#define B_    8
#define LQ    4096
#define LK    4096
#define D_    512
#define LSEL  2744
#define MPAD  2816
#define SCALE 0.04419417382415922f   // 1/sqrt(512)

// ============================ device scratch ================================
__device__ __half g_qh[B_ * LQ * D_];           // Q*SCALE fp16
__device__ __half g_kh[B_ * LK * D_];           // K fp16
__device__ __half g_vth[B_ * D_ * LK];          // V^T fp16 [b][d][k]
__device__ __half g_E[(size_t)B_ * MPAD * LK];  // exp(S) fp16 [b][m][k]
__device__ __half g_kt[(size_t)B_ * D_ * LK];   // K^T fp16 [b][d][k]
__device__ float  g_Zpart[B_ * MPAD * 32];
__device__ float  g_Z[B_ * MPAD];
__device__ float  g_kreduce[B_ * D_];
__device__ double g_meanpart[B_ * 128 * D_];
__device__ float  g_meanvals[B_ * D_];
__device__ float  g_sqk[B_ * LQ];
__device__ float  g_thresh[B_];
__device__ int    g_selidx[B_ * LSEL];
__device__ int    g_selcnt[B_];

// ============================ PTX helpers ===================================
__device__ __forceinline__ uint32_t smem_u32(const void* p) {
    uint32_t a;
    asm("{ .reg .u64 t; cvta.to.shared.u64 t, %1; cvt.u32.u64 %0, t; }" : "=r"(a) : "l"(p));
    return a;
}

#define CP_ASYNC16(dst, src) \
    asm volatile("cp.async.cg.shared.global [%0], [%1], 16;" :: "r"(dst), "l"(src) : "memory")
#define CP_COMMIT() asm volatile("cp.async.commit_group;" ::: "memory")
#define CP_WAIT2()  asm volatile("cp.async.wait_group 2;" ::: "memory")
#define CP_WAIT0()  asm volatile("cp.async.wait_group 0;" ::: "memory")

#define LDSM4(r, a) \
    asm volatile("ldmatrix.sync.aligned.m8n8.x4.shared.b16 {%0,%1,%2,%3}, [%4];" \
        : "=r"((r)[0]), "=r"((r)[1]), "=r"((r)[2]), "=r"((r)[3]) : "r"(a))

#define MMAH(d, a, b0, b1) \
    asm volatile("mma.sync.aligned.m16n8k16.row.col.f32.f16.f16.f32 " \
        "{%0,%1,%2,%3}, {%4,%5,%6,%7}, {%8,%9}, {%0,%1,%2,%3};" \
        : "+f"((d)[0]), "+f"((d)[1]), "+f"((d)[2]), "+f"((d)[3]) \
        : "r"((a)[0]), "r"((a)[1]), "r"((a)[2]), "r"((a)[3]), "r"(b0), "r"(b1))

// swizzled addr inside one tile of 128-byte rows (SW128)
__device__ __forceinline__ uint32_t swaddr(uint32_t base, int row, int kb) {
    uint32_t o = (uint32_t)(row * 128 + kb);
    return base + (o ^ ((o >> 3) & 0x70));
}

__device__ __forceinline__ unsigned f2sort(float f) {
    unsigned u = __float_as_uint(f);
    return (u & 0x80000000u) ? ~u : (u | 0x80000000u);
}
__device__ __forceinline__ float sort2f(unsigned u) {
    unsigned fb = (u & 0x80000000u) ? (u ^ 0x80000000u) : ~u;
    return __uint_as_float(fb);
}
__device__ __forceinline__ unsigned h2sort(unsigned hbits) {
    return (hbits & 0x8000u) ? (0xFFFFu & ~hbits) : (hbits | 0x8000u);
}
__device__ __forceinline__ float sort2h(unsigned u) {
    unsigned hb = (u & 0x8000u) ? (u ^ 0x8000u) : (0xFFFFu & ~u);
    __half h = __ushort_as_half((unsigned short)hb);
    return __half2float(h);
}

// =================== prep kernels ===========================================
__global__ void k_split_q(const float4* __restrict__ src) {
    size_t i = (size_t)blockIdx.x * 256 + threadIdx.x;
    float4 v = src[i];
    __half2* dh = (__half2*)g_qh;
    dh[2 * i]     = __floats2half2_rn(v.x * SCALE, v.y * SCALE);
    dh[2 * i + 1] = __floats2half2_rn(v.z * SCALE, v.w * SCALE);
}

__global__ void k_prep_k(const float* __restrict__ keys) {
    __shared__ float t[32][33];
    int b = blockIdx.z, d0 = blockIdx.x * 32, k0 = blockIdx.y * 32;
    int tx = threadIdx.x, ty = threadIdx.y;
#pragma unroll
    for (int j = 0; j < 4; j++) {
        int kk = k0 + ty + 8 * j;
        float f = keys[((size_t)b * LK + kk) * D_ + d0 + tx];
        t[ty + 8 * j][tx] = f;
        g_kh[((size_t)b * LK + kk) * D_ + d0 + tx] = __float2half_rn(f);
    }
    __syncthreads();
#pragma unroll
    for (int j = 0; j < 4; j++)
        g_kt[((size_t)b * D_ + d0 + ty + 8 * j) * LK + k0 + tx] =
            __float2half_rn(t[tx][ty + 8 * j]);
}

__global__ void k_prep_v(const float* __restrict__ v) {
    __shared__ float t[32][33];
    __shared__ float ps[8][33];
    int b = blockIdx.z, d0 = blockIdx.x * 32, kblk = blockIdx.y;
    int k0 = kblk * 32;
    int tx = threadIdx.x, ty = threadIdx.y;
#pragma unroll
    for (int j = 0; j < 4; j++)
        t[ty + 8 * j][tx] = v[((size_t)b * LK + k0 + ty + 8 * j) * D_ + d0 + tx];
    __syncthreads();
#pragma unroll
    for (int j = 0; j < 4; j++)
        g_vth[((size_t)b * D_ + d0 + ty + 8 * j) * LK + k0 + tx] =
            __float2half_rn(t[tx][ty + 8 * j]);
    float s = 0.f;
#pragma unroll
    for (int j = 0; j < 4; j++) s += t[ty * 4 + j][tx];
    ps[ty][tx] = s;
    __syncthreads();
    if (ty == 0) {
        double acc = 0.0;
#pragma unroll
        for (int j = 0; j < 8; j++) acc += (double)ps[j][tx];
        g_meanpart[((size_t)b * 128 + kblk) * D_ + d0 + tx] = acc;
    }
}

// =================== radix select (32-bit, exact) ===========================
__device__ void radix_select(unsigned* su, unsigned* hist,
                             unsigned* s_pref, unsigned* s_need, int want) {
    int tid = threadIdx.x;
    if (tid == 0) { *s_pref = 0; *s_need = (unsigned)want; }
    __syncthreads();
    unsigned pref = 0, need = (unsigned)want;
    for (int pass = 3; pass >= 0; pass--) {
        if (tid < 256) hist[tid] = 0;
        __syncthreads();
        for (int i = tid; i < 4096; i += 256) {
            unsigned u = su[i];
            unsigned hi = (pass == 3) ? 0u : (u >> ((pass + 1) * 8));
            if (hi == pref) atomicAdd(&hist[(u >> (pass * 8)) & 255], 1);
        }
        __syncthreads();
        if (tid == 0) {
            unsigned cum = 0;
            for (int bin = 255; bin >= 0; bin--) {
                unsigned c = hist[bin];
                if (cum + c >= need) {
                    *s_need = need - cum;
                    *s_pref = (pref << 8) | (unsigned)bin;
                    break;
                }
                cum += c;
            }
        }
        __syncthreads();
        pref = *s_pref; need = *s_need;
        __syncthreads();
    }
}

// =================== K_reduce: fp16 keys, 2-pass radix, per-warp hist =======
__global__ void k_kreduce() {
    __shared__ unsigned short su[4096];
    __shared__ unsigned hist8[8][256];
    __shared__ unsigned hist[256];
    __shared__ unsigned s_pref, s_need;
    __shared__ double red[256];
    int bd = blockIdx.x;
    int tid = threadIdx.x;
    int wid = tid >> 5;
    const __half2* kp = (const __half2*)(g_kt + (size_t)bd * LK);
    for (int i = tid; i < 2048; i += 256) {
        __half2 h2 = kp[i];
        unsigned bits = *(const unsigned*)&h2;
        su[2 * i]     = (unsigned short)h2sort(bits & 0xFFFFu);
        su[2 * i + 1] = (unsigned short)h2sort(bits >> 16);
        hist8[(i >> 8)][i & 255] = 0;   // zero all 8*256 entries
    }
    __syncthreads();
    // pass 1: high byte, per-warp hist (cuts atomic contention 8x)
    for (int i = tid; i < 4096; i += 256) atomicAdd(&hist8[wid][su[i] >> 8], 1);
    __syncthreads();
    if (tid < 256) {
        unsigned s = 0;
#pragma unroll
        for (int w = 0; w < 8; w++) s += hist8[w][tid];
        hist[tid] = s;
    }
    if (tid == 0) { s_pref = 0; s_need = LSEL; }
    __syncthreads();
    if (tid == 0) {
        unsigned cum = 0, need = LSEL;
        for (int bin = 255; bin >= 0; bin--) {
            unsigned c = hist[bin];
            if (cum + c >= need) { s_need = need - cum; s_pref = (unsigned)bin; break; }
            cum += c;
        }
    }
    __syncthreads();
    unsigned pref = s_pref;
    if (tid < 256) hist[tid] = 0;
    __syncthreads();
    // pass 2: low byte within pref (few matches -> low contention)
    for (int i = tid; i < 4096; i += 256) {
        unsigned u = su[i];
        if ((u >> 8) == pref) atomicAdd(&hist[u & 255], 1);
    }
    __syncthreads();
    if (tid == 0) {
        unsigned cum = 0, need = s_need;
        for (int bin = 255; bin >= 0; bin--) {
            unsigned c = hist[bin];
            if (cum + c >= need) { s_need = need - cum; s_pref = (pref << 8) | (unsigned)bin; break; }
            cum += c;
        }
    }
    __syncthreads();
    unsigned tu = s_pref, need = s_need;
    double acc = 0.0;
    for (int i = tid; i < 4096; i += 256) {
        unsigned u = su[i];
        if (u > tu) acc += (double)sort2h(u);
    }
    red[tid] = acc;
    __syncthreads();
    for (int t = 128; t > 0; t >>= 1) {
        if (tid < t) red[tid] += red[tid + t];
        __syncthreads();
    }
    if (tid == 0)
        g_kreduce[bd] = (float)((red[0] + (double)need * (double)sort2h(tu)) / (double)LSEL);
}

__global__ void k_meanfin() {
    int b = blockIdx.x, d = threadIdx.x;
    double s = 0.0;
    for (int j = 0; j < 128; j++) s += g_meanpart[((size_t)b * 128 + j) * D_ + d];
    g_meanvals[b * D_ + d] = (float)(s / (double)LK);
}

// =================== sqk = Q . K_reduce (fp64, exact path) ===================
__global__ void k_sqk(const float* __restrict__ queries) {
    __shared__ float kr[D_];
    int warp = threadIdx.x >> 5, lane = threadIdx.x & 31;
    int qflat = blockIdx.x * 8 + warp;
    int b = qflat >> 12;
    for (int i = threadIdx.x; i < D_; i += 256) kr[i] = g_kreduce[b * D_ + i];
    __syncthreads();
    const float* qp = queries + (size_t)qflat * D_;
    double acc = 0.0;
#pragma unroll
    for (int j = 0; j < 16; j++) {
        int d = lane + 32 * j;
        acc += (double)qp[d] * (double)kr[d];
    }
    for (int off = 16; off; off >>= 1) acc += __shfl_down_sync(0xffffffffu, acc, off);
    if (lane == 0) g_sqk[qflat] = (float)acc;
}

// =================== selection (exact 32-bit radix) =========================
__global__ void k_thresh() {
    __shared__ unsigned su[4096];
    __shared__ unsigned hist[256];
    __shared__ unsigned s_pref, s_need;
    int b = blockIdx.x, tid = threadIdx.x;
    for (int i = tid; i < 4096; i += 256) su[i] = f2sort(g_sqk[b * LQ + i]);
    __syncthreads();
    radix_select(su, hist, &s_pref, &s_need, LSEL);
    if (tid == 0) {
        g_thresh[b] = sort2f(s_pref);
        g_selcnt[b] = 0;
    }
}

__global__ void k_compact() {
    int qflat = blockIdx.x * 256 + threadIdx.x;
    int b = qflat >> 12;
    if (g_sqk[qflat] >= g_thresh[b]) {
        int pos = atomicAdd(&g_selcnt[b], 1);
        if (pos < LSEL) g_selidx[b * LSEL + pos] = qflat & 4095;
    }
}

__global__ void k_fill(float* __restrict__ out) {
    int r = blockIdx.x, b = r >> 12;
    if (g_sqk[r] < g_thresh[b]) {
        const float4* mv = (const float4*)(g_meanvals + b * D_);
        float4* op = (float4*)(out + (size_t)r * D_);
        op[threadIdx.x] = mv[threadIdx.x];
    }
}

// =================== tile compute: CTA 128x256, 16 warps (4Mx4N) ============
// stage: A 128 rows @ st (16KB), B 256 rows @ st+16384 (32KB); SW128 rows.
// warp tile 32x64; d[2][8][4].
__device__ __forceinline__ void gemm_stage(uint32_t st, int wm, int wn, int lane,
                                           float d[2][8][4]) {
    int rA = wm * 32 + (lane & 15);
    int kA = (lane >> 4) * 16;
    int rB = wn * 64 + (lane & 7) + ((lane >> 4) << 3);
    int kB = ((lane >> 3) & 1) * 16;
#pragma unroll
    for (int t = 0; t < 4; t++) {
        uint32_t a0[4], a1[4];
        LDSM4(a0, swaddr(st, rA, t * 32 + kA));
        LDSM4(a1, swaddr(st, rA + 16, t * 32 + kA));
#pragma unroll
        for (int p = 0; p < 4; p++) {
            uint32_t bh[4];
            LDSM4(bh, swaddr(st + 16384, rB + p * 16, t * 32 + kB));
            MMAH(d[0][2 * p],     a0, bh[0], bh[1]);
            MMAH(d[0][2 * p + 1], a0, bh[2], bh[3]);
            MMAH(d[1][2 * p],     a1, bh[0], bh[1]);
            MMAH(d[1][2 * p + 1], a1, bh[2], bh[3]);
        }
    }
}

#define STAGE_SZ 49152
#define SMEM_G   (4 * STAGE_SZ)   // 192 KB, occ 1

// =================== GEMM 1: E = exp(Qsel@K^T), row-sum partials ============
__global__ void __launch_bounds__(512, 1) k_gemm_qk() {
    extern __shared__ char dsm[];
    __shared__ int srow[128];
    __shared__ float zsh[4][128];
    uint32_t sb = smem_u32(dsm);
    int tid = threadIdx.x;
    int b = blockIdx.z, m0 = blockIdx.y * 128, n0 = blockIdx.x * 256;

    if (tid < 128) {
        int m = m0 + tid;
        srow[tid] = g_selidx[b * LSEL + (m < LSEL ? m : 0)];
    }
    __syncthreads();

    const __half* baseA = g_qh + (size_t)b * LQ * D_;
    const __half* baseB = g_kh + ((size_t)b * LK + n0) * D_;

#define QK_FILL(s, k) do {                                                     \
    uint32_t st_ = sb + (s) * STAGE_SZ;                                        \
    int k0_ = (k) * 64;                                                        \
    for (int idx = tid; idx < 3072; idx += 512) {                              \
        if (idx < 1024) {                                                      \
            int r_ = idx >> 3, seg_ = idx & 7;                                 \
            CP_ASYNC16(swaddr(st_, r_, seg_ * 16),                             \
                       baseA + (size_t)srow[r_] * D_ + k0_ + seg_ * 8);        \
        } else {                                                               \
            int i2 = idx - 1024;                                               \
            int r_ = i2 >> 3, seg_ = i2 & 7;                                   \
            CP_ASYNC16(swaddr(st_ + 16384, r_, seg_ * 16),                     \
                       baseB + (size_t)r_ * D_ + k0_ + seg_ * 8);              \
        }                                                                      \
    } CP_COMMIT(); } while (0)

    QK_FILL(0, 0); QK_FILL(1, 1); QK_FILL(2, 2);

    int lane = tid & 31, w = tid >> 5, wm = w >> 2, wn = w & 3;
    float d[2][8][4] = {};

    for (int k = 0; k < 8; k++) {
        int s = k & 3;
        if (k == 7) { CP_WAIT0(); } else { CP_WAIT2(); }
        __syncthreads();
        gemm_stage(sb + s * STAGE_SZ, wm, wn, lane, d);
        __syncthreads();
        if (k + 3 < 8) QK_FILL((k + 3) & 3, k + 3);
    }

    float rs[2][2] = {};
#pragma unroll
    for (int i = 0; i < 2; i++)
#pragma unroll
        for (int j = 0; j < 8; j++) {
            d[i][j][0] = __expf(d[i][j][0]);
            d[i][j][1] = __expf(d[i][j][1]);
            d[i][j][2] = __expf(d[i][j][2]);
            d[i][j][3] = __expf(d[i][j][3]);
            rs[i][0] += d[i][j][0] + d[i][j][1];
            rs[i][1] += d[i][j][2] + d[i][j][3];
        }
#pragma unroll
    for (int i = 0; i < 2; i++)
#pragma unroll
        for (int h = 0; h < 2; h++) {
            rs[i][h] += __shfl_xor_sync(0xffffffffu, rs[i][h], 1);
            rs[i][h] += __shfl_xor_sync(0xffffffffu, rs[i][h], 2);
        }
    // accumulate partial row sums across the 4 wn columns via smem
    if (tid < 128) { zsh[0][tid] = 0.f; zsh[1][tid] = 0.f; zsh[2][tid] = 0.f; zsh[3][tid] = 0.f; }
    __syncthreads();
    if ((lane & 3) == 0) {
        int rl = wm * 32 + (lane >> 2);
        zsh[wn][rl]      = rs[0][0];
        zsh[wn][rl + 8]  = rs[0][1];
        zsh[wn][rl + 16] = rs[1][0];
        zsh[wn][rl + 24] = rs[1][1];
    }

    int mBase = m0 + wm * 32, nBase = n0 + wn * 64;
#pragma unroll
    for (int i = 0; i < 2; i++) {
        int r = mBase + i * 16 + (lane >> 2);
#pragma unroll
        for (int j = 0; j < 8; j++) {
            int c = nBase + j * 8 + (lane & 3) * 2;
            if (r < LSEL)
                *(__half2*)(g_E + ((size_t)b * MPAD + r) * LK + c) =
                    __floats2half2_rn(d[i][j][0], d[i][j][1]);
            if (r + 8 < LSEL)
                *(__half2*)(g_E + ((size_t)b * MPAD + r + 8) * LK + c) =
                    __floats2half2_rn(d[i][j][2], d[i][j][3]);
        }
    }
    __syncthreads();
    if (tid < 128) {
        float z = zsh[0][tid] + zsh[1][tid] + zsh[2][tid] + zsh[3][tid];
        g_Zpart[(size_t)(b * MPAD + m0 + tid) * 16 + blockIdx.x] = z;
    }
}

// =================== Z reduction ============================================
__global__ void k_zsum() {
    int m = blockIdx.x * 256 + threadIdx.x;
    const float* p = g_Zpart + (size_t)m * 16;
    float s = 0.f;
#pragma unroll
    for (int i = 0; i < 16; i++) s += p[i];
    g_Z[m] = s;
}

// =================== GEMM 2: O = (E @ V)/Z, scatter =========================
__global__ void __launch_bounds__(512, 1) k_gemm_pv(float* __restrict__ out) {
    extern __shared__ char dsm[];
    __shared__ int srow[128];
    uint32_t sb = smem_u32(dsm);
    int tid = threadIdx.x;
    int b = blockIdx.z, m0 = blockIdx.y * 128, n0 = blockIdx.x * 256;

    if (tid < 128) {
        int m = m0 + tid;
        srow[tid] = g_selidx[b * LSEL + (m < LSEL ? m : 0)];
    }
    __syncthreads();

    const __half* baseA = g_E + ((size_t)b * MPAD + m0) * LK;
    const __half* baseB = g_vth + ((size_t)b * D_ + n0) * LK;

#define PV_FILL(s, k) do {                                                     \
    uint32_t st_ = sb + (s) * STAGE_SZ;                                        \
    int k0_ = (k) * 64;                                                        \
    for (int idx = tid; idx < 3072; idx += 512) {                              \
        if (idx < 1024) {                                                      \
            int r_ = idx >> 3, seg_ = idx & 7;                                 \
            CP_ASYNC16(swaddr(st_, r_, seg_ * 16),                             \
                       baseA + (size_t)r_ * LK + k0_ + seg_ * 8);              \
        } else {                                                               \
            int i2 = idx - 1024;                                               \
            int r_ = i2 >> 3, seg_ = i2 & 7;                                   \
            CP_ASYNC16(swaddr(st_ + 16384, r_, seg_ * 16),                     \
                       baseB + (size_t)r_ * LK + k0_ + seg_ * 8);              \
        }                                                                      \
    } CP_COMMIT(); } while (0)

    PV_FILL(0, 0); PV_FILL(1, 1); PV_FILL(2, 2);

    int lane = tid & 31, w = tid >> 5, wm = w >> 2, wn = w & 3;
    float d[2][8][4] = {};

    for (int k = 0; k < 64; k++) {
        int s = k & 3;
        if (k == 63) { CP_WAIT0(); } else { CP_WAIT2(); }
        __syncthreads();
        gemm_stage(sb + s * STAGE_SZ, wm, wn, lane, d);
        __syncthreads();
        if (k + 3 < 64) PV_FILL((k + 3) & 3, k + 3);
    }

    int nBase = n0 + wn * 64;
#pragma unroll
    for (int i = 0; i < 2; i++) {
        int lr = wm * 32 + i * 16 + (lane >> 2);
        int m = m0 + lr;
        float zi0 = 1.0f / g_Z[b * MPAD + m];
        float zi1 = 1.0f / g_Z[b * MPAD + m + 8];
        int q0 = srow[lr], q1 = srow[lr + 8];
#pragma unroll
        for (int j = 0; j < 8; j++) {
            int c = nBase + j * 8 + (lane & 3) * 2;
            if (m < LSEL)
                *(float2*)(out + ((size_t)b * LQ + q0) * D_ + c) =
                    float2{d[i][j][0] * zi0, d[i][j][1] * zi0};
            if (m + 8 < LSEL)
                *(float2*)(out + ((size_t)b * LQ + q1) * D_ + c) =
                    float2{d[i][j][2] * zi1, d[i][j][3] * zi1};
        }
    }
}

// =================== launch ==================================================
extern "C" void kernel_launch(void* const* d_in, const int* in_sizes, int n_in,
                              void* d_out, int out_size) {
    const float* q = (const float*)d_in[0];
    const float* k = (const float*)d_in[1];
    const float* v = (const float*)d_in[2];
    float* out = (float*)d_out;

    cudaFuncSetAttribute(k_gemm_qk, cudaFuncAttributeMaxDynamicSharedMemorySize, SMEM_G);
    cudaFuncSetAttribute(k_gemm_pv, cudaFuncAttributeMaxDynamicSharedMemorySize, SMEM_G);

    k_split_q<<<16384, 256>>>((const float4*)q);
    k_prep_k<<<dim3(16, 128, 8), dim3(32, 8)>>>(k);
    k_prep_v<<<dim3(16, 128, 8), dim3(32, 8)>>>(v);

    k_kreduce<<<B_ * D_, 256>>>();
    k_meanfin<<<B_, 512>>>();
    k_sqk<<<B_ * LQ / 8, 256>>>(q);
    k_thresh<<<B_, 256>>>();
    k_compact<<<B_ * LQ / 256, 256>>>();
    k_fill<<<B_ * LQ, 128>>>(out);

    dim3 g1(LK / 256, (LSEL + 127) / 128, B_);   // 16 x 22 x 8
    k_gemm_qk<<<g1, 512, SMEM_G>>>();

    k_zsum<<<B_ * MPAD / 256, 256>>>();

    dim3 g2(D_ / 256, (LSEL + 127) / 128, B_);   // 2 x 22 x 8
    k_gemm_pv<<<g2, 512, SMEM_G>>>(out);
}

// round 11
// speedup vs baseline: 1.2069x; 1.2069x over previous
#include <cuda_runtime.h>
#include <cuda_fp16.h>
#include <cstdint>

#define B_    8
#define LQ    4096
#define LK    4096
#define D_    512
#define LSEL  2744
#define MPAD  2816
#define SCALE 0.04419417382415922f   // 1/sqrt(512)

// ============================ device scratch ================================
__device__ __half g_qh[B_ * LQ * D_];           // Q*SCALE fp16
__device__ __half g_kh[B_ * LK * D_];           // K fp16
__device__ __half g_vth[B_ * D_ * LK];          // V^T fp16 [b][d][k]
__device__ __half g_E[(size_t)B_ * MPAD * LK];  // exp(S) fp16 [b][m][k]
__device__ __half g_kt[(size_t)B_ * D_ * LK];   // K^T fp16 [b][d][k]
__device__ float  g_Zpart[B_ * MPAD * 32];
__device__ float  g_Z[B_ * MPAD];
__device__ float  g_kreduce[B_ * D_];
__device__ double g_meanpart[B_ * 128 * D_];
__device__ float  g_meanvals[B_ * D_];
__device__ float  g_sqk[B_ * LQ];
__device__ float  g_thresh[B_];
__device__ int    g_selidx[B_ * LSEL];
__device__ int    g_selcnt[B_];

// ============================ PTX helpers ===================================
__device__ __forceinline__ uint32_t smem_u32(const void* p) {
    uint32_t a;
    asm("{ .reg .u64 t; cvta.to.shared.u64 t, %1; cvt.u32.u64 %0, t; }" : "=r"(a) : "l"(p));
    return a;
}

#define CP_ASYNC16(dst, src) \
    asm volatile("cp.async.cg.shared.global [%0], [%1], 16;" :: "r"(dst), "l"(src) : "memory")
#define CP_COMMIT() asm volatile("cp.async.commit_group;" ::: "memory")
#define CP_WAIT2()  asm volatile("cp.async.wait_group 2;" ::: "memory")
#define CP_WAIT0()  asm volatile("cp.async.wait_group 0;" ::: "memory")

#define LDSM4(r, a) \
    asm volatile("ldmatrix.sync.aligned.m8n8.x4.shared.b16 {%0,%1,%2,%3}, [%4];" \
        : "=r"((r)[0]), "=r"((r)[1]), "=r"((r)[2]), "=r"((r)[3]) : "r"(a))

#define MMAH(d, a, b0, b1) \
    asm volatile("mma.sync.aligned.m16n8k16.row.col.f32.f16.f16.f32 " \
        "{%0,%1,%2,%3}, {%4,%5,%6,%7}, {%8,%9}, {%0,%1,%2,%3};" \
        : "+f"((d)[0]), "+f"((d)[1]), "+f"((d)[2]), "+f"((d)[3]) \
        : "r"((a)[0]), "r"((a)[1]), "r"((a)[2]), "r"((a)[3]), "r"(b0), "r"(b1))

// swizzled addr inside one tile of 128-byte rows (SW128)
__device__ __forceinline__ uint32_t swaddr(uint32_t base, int row, int kb) {
    uint32_t o = (uint32_t)(row * 128 + kb);
    return base + (o ^ ((o >> 3) & 0x70));
}

__device__ __forceinline__ unsigned f2sort(float f) {
    unsigned u = __float_as_uint(f);
    return (u & 0x80000000u) ? ~u : (u | 0x80000000u);
}
__device__ __forceinline__ float sort2f(unsigned u) {
    unsigned fb = (u & 0x80000000u) ? (u ^ 0x80000000u) : ~u;
    return __uint_as_float(fb);
}
__device__ __forceinline__ unsigned h2sort(unsigned hbits) {
    return (hbits & 0x8000u) ? (0xFFFFu & ~hbits) : (hbits | 0x8000u);
}
__device__ __forceinline__ float sort2h(unsigned u) {
    unsigned hb = (u & 0x8000u) ? (u ^ 0x8000u) : (0xFFFFu & ~u);
    __half h = __ushort_as_half((unsigned short)hb);
    return __half2float(h);
}

// =================== prep kernels ===========================================
__global__ void k_split_q(const float4* __restrict__ src) {
    size_t i = (size_t)blockIdx.x * 256 + threadIdx.x;
    float4 v = src[i];
    __half2* dh = (__half2*)g_qh;
    dh[2 * i]     = __floats2half2_rn(v.x * SCALE, v.y * SCALE);
    dh[2 * i + 1] = __floats2half2_rn(v.z * SCALE, v.w * SCALE);
}

__global__ void k_prep_k(const float* __restrict__ keys) {
    __shared__ float t[32][33];
    int b = blockIdx.z, d0 = blockIdx.x * 32, k0 = blockIdx.y * 32;
    int tx = threadIdx.x, ty = threadIdx.y;
#pragma unroll
    for (int j = 0; j < 4; j++) {
        int kk = k0 + ty + 8 * j;
        float f = keys[((size_t)b * LK + kk) * D_ + d0 + tx];
        t[ty + 8 * j][tx] = f;
        g_kh[((size_t)b * LK + kk) * D_ + d0 + tx] = __float2half_rn(f);
    }
    __syncthreads();
#pragma unroll
    for (int j = 0; j < 4; j++)
        g_kt[((size_t)b * D_ + d0 + ty + 8 * j) * LK + k0 + tx] =
            __float2half_rn(t[tx][ty + 8 * j]);
}

__global__ void k_prep_v(const float* __restrict__ v) {
    __shared__ float t[32][33];
    __shared__ float ps[8][33];
    int b = blockIdx.z, d0 = blockIdx.x * 32, kblk = blockIdx.y;
    int k0 = kblk * 32;
    int tx = threadIdx.x, ty = threadIdx.y;
#pragma unroll
    for (int j = 0; j < 4; j++)
        t[ty + 8 * j][tx] = v[((size_t)b * LK + k0 + ty + 8 * j) * D_ + d0 + tx];
    __syncthreads();
#pragma unroll
    for (int j = 0; j < 4; j++)
        g_vth[((size_t)b * D_ + d0 + ty + 8 * j) * LK + k0 + tx] =
            __float2half_rn(t[tx][ty + 8 * j]);
    float s = 0.f;
#pragma unroll
    for (int j = 0; j < 4; j++) s += t[ty * 4 + j][tx];
    ps[ty][tx] = s;
    __syncthreads();
    if (ty == 0) {
        double acc = 0.0;
#pragma unroll
        for (int j = 0; j < 8; j++) acc += (double)ps[j][tx];
        g_meanpart[((size_t)b * 128 + kblk) * D_ + d0 + tx] = acc;
    }
}

// =================== K_reduce: fp16 keys, 2-pass radix (hist1 from regs) ====
__global__ void k_kreduce() {
    __shared__ unsigned short su[4096];
    __shared__ unsigned hist[256];
    __shared__ unsigned s_pref, s_need;
    __shared__ double red[256];
    int bd = blockIdx.x;
    int tid = threadIdx.x;
    const __half2* kp = (const __half2*)(g_kt + (size_t)bd * LK);

    if (tid == 0) { s_pref = 0; s_need = LSEL; }
    hist[tid] = 0;
    __syncthreads();

    // load + convert + store su + pass-1 histogram (from registers)
#pragma unroll
    for (int j = 0; j < 8; j++) {
        int i = tid + 256 * j;
        __half2 h2 = kp[i];
        unsigned bits = *(const unsigned*)&h2;
        unsigned u0 = h2sort(bits & 0xFFFFu);
        unsigned u1 = h2sort(bits >> 16);
        su[2 * i]     = (unsigned short)u0;
        su[2 * i + 1] = (unsigned short)u1;
        atomicAdd(&hist[u0 >> 8], 1);
        atomicAdd(&hist[u1 >> 8], 1);
    }
    __syncthreads();
    if (tid == 0) {
        unsigned cum = 0, need = LSEL;
        for (int bin = 255; bin >= 0; bin--) {
            unsigned c = hist[bin];
            if (cum + c >= need) { s_need = need - cum; s_pref = (unsigned)bin; break; }
            cum += c;
        }
    }
    __syncthreads();
    unsigned pref = s_pref;
    hist[tid] = 0;
    __syncthreads();
    // pass 2: low byte within pref
    for (int i = tid; i < 4096; i += 256) {
        unsigned u = su[i];
        if ((u >> 8) == pref) atomicAdd(&hist[u & 255], 1);
    }
    __syncthreads();
    if (tid == 0) {
        unsigned cum = 0, need = s_need;
        for (int bin = 255; bin >= 0; bin--) {
            unsigned c = hist[bin];
            if (cum + c >= need) { s_need = need - cum; s_pref = (pref << 8) | (unsigned)bin; break; }
            cum += c;
        }
    }
    __syncthreads();
    unsigned tu = s_pref, need = s_need;
    double acc = 0.0;
    for (int i = tid; i < 4096; i += 256) {
        unsigned u = su[i];
        if (u > tu) acc += (double)sort2h(u);
    }
    red[tid] = acc;
    __syncthreads();
    for (int t = 128; t > 0; t >>= 1) {
        if (tid < t) red[tid] += red[tid + t];
        __syncthreads();
    }
    if (tid == 0)
        g_kreduce[bd] = (float)((red[0] + (double)need * (double)sort2h(tu)) / (double)LSEL);
}

__global__ void k_meanfin() {
    int b = blockIdx.x, d = threadIdx.x;
    double s = 0.0;
    for (int j = 0; j < 128; j++) s += g_meanpart[((size_t)b * 128 + j) * D_ + d];
    g_meanvals[b * D_ + d] = (float)(s / (double)LK);
}

// =================== sqk = Q . K_reduce (fp64, exact path) ===================
__global__ void k_sqk(const float* __restrict__ queries) {
    __shared__ float kr[D_];
    int warp = threadIdx.x >> 5, lane = threadIdx.x & 31;
    int qflat = blockIdx.x * 8 + warp;
    int b = qflat >> 12;
    for (int i = threadIdx.x; i < D_; i += 256) kr[i] = g_kreduce[b * D_ + i];
    __syncthreads();
    const float* qp = queries + (size_t)qflat * D_;
    double acc = 0.0;
#pragma unroll
    for (int j = 0; j < 16; j++) {
        int d = lane + 32 * j;
        acc += (double)qp[d] * (double)kr[d];
    }
    for (int off = 16; off; off >>= 1) acc += __shfl_down_sync(0xffffffffu, acc, off);
    if (lane == 0) g_sqk[qflat] = (float)acc;
}

// =================== threshold + compaction (fused, exact 32-bit radix) =====
__global__ void k_thresh() {
    __shared__ unsigned su[4096];
    __shared__ unsigned hist[256];
    __shared__ unsigned s_pref, s_need;
    int b = blockIdx.x, tid = threadIdx.x;
    if (tid == 0) { s_pref = 0; s_need = LSEL; g_selcnt[b] = 0; }
    __syncthreads();
    for (int i = tid; i < 4096; i += 256) su[i] = f2sort(g_sqk[b * LQ + i]);
    __syncthreads();
    unsigned pref = 0, need = LSEL;
    for (int pass = 3; pass >= 0; pass--) {
        hist[tid] = 0;
        __syncthreads();
        for (int i = tid; i < 4096; i += 256) {
            unsigned u = su[i];
            unsigned hi = (pass == 3) ? 0u : (u >> ((pass + 1) * 8));
            if (hi == pref) atomicAdd(&hist[(u >> (pass * 8)) & 255], 1);
        }
        __syncthreads();
        if (tid == 0) {
            unsigned cum = 0;
            for (int bin = 255; bin >= 0; bin--) {
                unsigned c = hist[bin];
                if (cum + c >= need) {
                    s_need = need - cum;
                    s_pref = (pref << 8) | (unsigned)bin;
                    break;
                }
                cum += c;
            }
        }
        __syncthreads();
        pref = s_pref; need = s_need;
        __syncthreads();
    }
    unsigned tu = s_pref;
    if (tid == 0) g_thresh[b] = sort2f(tu);
    // compaction: same >= semantics as float compare on g_sqk vs thresh
    for (int i = tid; i < 4096; i += 256) {
        if (su[i] >= tu) {
            int pos = atomicAdd(&g_selcnt[b], 1);
            if (pos < LSEL) g_selidx[b * LSEL + pos] = i;
        }
    }
}

__global__ void k_fill(float* __restrict__ out) {
    int r = blockIdx.x, b = r >> 12;
    if (g_sqk[r] < g_thresh[b]) {
        const float4* mv = (const float4*)(g_meanvals + b * D_);
        float4* op = (float4*)(out + (size_t)r * D_);
        op[threadIdx.x] = mv[threadIdx.x];
    }
}

// =================== 1-pass fp16 tile compute (128x128, warp 32x64) =========
__device__ __forceinline__ void gemm_stage1(uint32_t st, int wm, int wn, int lane,
                                            float d[2][8][4]) {
    int rA = wm * 32 + (lane & 15);
    int kA = (lane >> 4) * 16;
    int rB = wn * 64 + (lane & 7) + ((lane >> 4) << 3);
    int kB = ((lane >> 3) & 1) * 16;
#pragma unroll
    for (int t = 0; t < 4; t++) {
        uint32_t a0[4], a1[4];
        LDSM4(a0, swaddr(st, rA, t * 32 + kA));
        LDSM4(a1, swaddr(st, rA + 16, t * 32 + kA));
#pragma unroll
        for (int p = 0; p < 4; p++) {
            uint32_t bh[4];
            LDSM4(bh, swaddr(st + 16384, rB + p * 16, t * 32 + kB));
            MMAH(d[0][2 * p],     a0, bh[0], bh[1]);
            MMAH(d[0][2 * p + 1], a0, bh[2], bh[3]);
            MMAH(d[1][2 * p],     a1, bh[0], bh[1]);
            MMAH(d[1][2 * p + 1], a1, bh[2], bh[3]);
        }
    }
}

#define SMEM_DYN (3 * 32768)

// =================== GEMM 1: E = exp(Qsel@K^T), row-sum partials ============
__global__ void __launch_bounds__(256, 2) k_gemm_qk() {
    extern __shared__ char dsm[];
    __shared__ int srow[128];
    __shared__ float zsh[2][128];
    uint32_t sb = smem_u32(dsm);
    int tid = threadIdx.x;
    int b = blockIdx.z, m0 = blockIdx.y * 128, n0 = blockIdx.x * 128;

    if (tid < 128) {
        int m = m0 + tid;
        srow[tid] = g_selidx[b * LSEL + (m < LSEL ? m : 0)];
    }
    __syncthreads();

    const __half* baseA = g_qh + (size_t)b * LQ * D_;
    const __half* baseB = g_kh + ((size_t)b * LK + n0) * D_;

#define QK_FILL(s, k) do {                                                     \
    uint32_t st_ = sb + (s) * 32768;                                           \
    int k0_ = (k) * 64;                                                        \
    for (int idx = tid; idx < 2048; idx += 256) {                              \
        int tile_ = idx >> 10, r_ = (idx >> 3) & 127, seg_ = idx & 7;          \
        const __half* src_ = (tile_ == 0)                                      \
            ? baseA + (size_t)srow[r_] * D_ + k0_ + seg_ * 8                   \
            : baseB + (size_t)r_ * D_ + k0_ + seg_ * 8;                        \
        CP_ASYNC16(swaddr(st_ + tile_ * 16384, r_, seg_ * 16), src_);          \
    } CP_COMMIT(); } while (0)

    QK_FILL(0, 0); QK_FILL(1, 1); QK_FILL(2, 2);

    int lane = tid & 31, w = tid >> 5, wm = w >> 1, wn = w & 1;
    float d[2][8][4] = {};

    for (int k = 0; k < 8; k++) {
        int s = k % 3;
        if (k == 7) { CP_WAIT0(); } else { CP_WAIT2(); }
        __syncthreads();
        gemm_stage1(sb + s * 32768, wm, wn, lane, d);
        __syncthreads();
        if (k + 3 < 8) QK_FILL(s, k + 3);
    }

    float rs[2][2] = {};
#pragma unroll
    for (int i = 0; i < 2; i++)
#pragma unroll
        for (int j = 0; j < 8; j++) {
            d[i][j][0] = __expf(d[i][j][0]);
            d[i][j][1] = __expf(d[i][j][1]);
            d[i][j][2] = __expf(d[i][j][2]);
            d[i][j][3] = __expf(d[i][j][3]);
            rs[i][0] += d[i][j][0] + d[i][j][1];
            rs[i][1] += d[i][j][2] + d[i][j][3];
        }
#pragma unroll
    for (int i = 0; i < 2; i++)
#pragma unroll
        for (int h = 0; h < 2; h++) {
            rs[i][h] += __shfl_xor_sync(0xffffffffu, rs[i][h], 1);
            rs[i][h] += __shfl_xor_sync(0xffffffffu, rs[i][h], 2);
        }
    if ((lane & 3) == 0) {
        int rl = wm * 32 + (lane >> 2);
        zsh[wn][rl]      = rs[0][0];
        zsh[wn][rl + 8]  = rs[0][1];
        zsh[wn][rl + 16] = rs[1][0];
        zsh[wn][rl + 24] = rs[1][1];
    }

    int mBase = m0 + wm * 32, nBase = n0 + wn * 64;
#pragma unroll
    for (int i = 0; i < 2; i++) {
        int r = mBase + i * 16 + (lane >> 2);
#pragma unroll
        for (int j = 0; j < 8; j++) {
            int c = nBase + j * 8 + (lane & 3) * 2;
            if (r < LSEL)
                *(__half2*)(g_E + ((size_t)b * MPAD + r) * LK + c) =
                    __floats2half2_rn(d[i][j][0], d[i][j][1]);
            if (r + 8 < LSEL)
                *(__half2*)(g_E + ((size_t)b * MPAD + r + 8) * LK + c) =
                    __floats2half2_rn(d[i][j][2], d[i][j][3]);
        }
    }
    __syncthreads();
    if (tid < 128) {
        float z = zsh[0][tid] + zsh[1][tid];
        g_Zpart[(size_t)(b * MPAD + m0 + tid) * 32 + blockIdx.x] = z;
    }
}

// =================== Z reduction ============================================
__global__ void k_zsum() {
    int m = blockIdx.x * 256 + threadIdx.x;
    const float* p = g_Zpart + (size_t)m * 32;
    float s = 0.f;
#pragma unroll
    for (int i = 0; i < 32; i++) s += p[i];
    g_Z[m] = s;
}

// =================== GEMM 2: O = (E @ V)/Z, scatter =========================
__global__ void __launch_bounds__(256, 2) k_gemm_pv(float* __restrict__ out) {
    extern __shared__ char dsm[];
    __shared__ int srow[128];
    uint32_t sb = smem_u32(dsm);
    int tid = threadIdx.x;
    int b = blockIdx.z, m0 = blockIdx.y * 128, n0 = blockIdx.x * 128;

    if (tid < 128) {
        int m = m0 + tid;
        srow[tid] = g_selidx[b * LSEL + (m < LSEL ? m : 0)];
    }
    __syncthreads();

    const __half* baseA = g_E + ((size_t)b * MPAD + m0) * LK;
    const __half* baseB = g_vth + ((size_t)b * D_ + n0) * LK;

#define PV_FILL(s, k) do {                                                     \
    uint32_t st_ = sb + (s) * 32768;                                           \
    int k0_ = (k) * 64;                                                        \
    for (int idx = tid; idx < 2048; idx += 256) {                              \
        int tile_ = idx >> 10, r_ = (idx >> 3) & 127, seg_ = idx & 7;          \
        const __half* src_ = (tile_ == 0)                                      \
            ? baseA + (size_t)r_ * LK + k0_ + seg_ * 8                         \
            : baseB + (size_t)r_ * LK + k0_ + seg_ * 8;                        \
        CP_ASYNC16(swaddr(st_ + tile_ * 16384, r_, seg_ * 16), src_);          \
    } CP_COMMIT(); } while (0)

    PV_FILL(0, 0); PV_FILL(1, 1); PV_FILL(2, 2);

    int lane = tid & 31, w = tid >> 5, wm = w >> 1, wn = w & 1;
    float d[2][8][4] = {};

    for (int k = 0; k < 64; k++) {
        int s = k % 3;
        if (k == 63) { CP_WAIT0(); } else { CP_WAIT2(); }
        __syncthreads();
        gemm_stage1(sb + s * 32768, wm, wn, lane, d);
        __syncthreads();
        if (k + 3 < 64) PV_FILL(s, k + 3);
    }

    int nBase = n0 + wn * 64;
#pragma unroll
    for (int i = 0; i < 2; i++) {
        int lr = wm * 32 + i * 16 + (lane >> 2);
        int m = m0 + lr;
        float zi0 = 1.0f / g_Z[b * MPAD + m];
        float zi1 = 1.0f / g_Z[b * MPAD + m + 8];
        int q0 = srow[lr], q1 = srow[lr + 8];
#pragma unroll
        for (int j = 0; j < 8; j++) {
            int c = nBase + j * 8 + (lane & 3) * 2;
            if (m < LSEL)
                *(float2*)(out + ((size_t)b * LQ + q0) * D_ + c) =
                    float2{d[i][j][0] * zi0, d[i][j][1] * zi0};
            if (m + 8 < LSEL)
                *(float2*)(out + ((size_t)b * LQ + q1) * D_ + c) =
                    float2{d[i][j][2] * zi1, d[i][j][3] * zi1};
        }
    }
}

// =================== launch ==================================================
extern "C" void kernel_launch(void* const* d_in, const int* in_sizes, int n_in,
                              void* d_out, int out_size) {
    const float* q = (const float*)d_in[0];
    const float* k = (const float*)d_in[1];
    const float* v = (const float*)d_in[2];
    float* out = (float*)d_out;

    cudaFuncSetAttribute(k_gemm_qk, cudaFuncAttributeMaxDynamicSharedMemorySize, SMEM_DYN);
    cudaFuncSetAttribute(k_gemm_pv, cudaFuncAttributeMaxDynamicSharedMemorySize, SMEM_DYN);

    k_split_q<<<16384, 256>>>((const float4*)q);
    k_prep_k<<<dim3(16, 128, 8), dim3(32, 8)>>>(k);
    k_prep_v<<<dim3(16, 128, 8), dim3(32, 8)>>>(v);

    k_kreduce<<<B_ * D_, 256>>>();
    k_meanfin<<<B_, 512>>>();
    k_sqk<<<B_ * LQ / 8, 256>>>(q);
    k_thresh<<<B_, 256>>>();
    k_fill<<<B_ * LQ, 128>>>(out);

    dim3 g1(LK / 128, (LSEL + 127) / 128, B_);   // 32 x 22 x 8
    k_gemm_qk<<<g1, 256, SMEM_DYN>>>();

    k_zsum<<<B_ * MPAD / 256, 256>>>();

    dim3 g2(D_ / 128, (LSEL + 127) / 128, B_);   // 4 x 22 x 8
    k_gemm_pv<<<g2, 256, SMEM_DYN>>>(out);
}

// round 12
// speedup vs baseline: 1.2071x; 1.0002x over previous
#include <cuda_runtime.h>
#include <cuda_fp16.h>
#include <cstdint>

#define B_    8
#define LQ    4096
#define LK    4096
#define D_    512
#define LSEL  2744
#define MPAD  2816
#define SCALE 0.04419417382415922f   // 1/sqrt(512)

// ============================ device scratch ================================
__device__ __half g_qh[B_ * LQ * D_];           // Q*SCALE fp16
__device__ __half g_kh[B_ * LK * D_];           // K fp16
__device__ __half g_vth[B_ * D_ * LK];          // V^T fp16 [b][d][k]
__device__ __half g_E[(size_t)B_ * MPAD * LK];  // exp(S) fp16 [b][m][k]
__device__ __half g_kt[(size_t)B_ * D_ * LK];   // K^T fp16 [b][d][k]
__device__ float  g_Zpart[B_ * MPAD * 32];
__device__ float  g_kreduce[B_ * D_];
__device__ double g_meanpart[B_ * 128 * D_];
__device__ float  g_meanvals[B_ * D_];
__device__ float  g_sqk[B_ * LQ];
__device__ float  g_thresh[B_];
__device__ int    g_selidx[B_ * LSEL];
__device__ int    g_selcnt[B_];

// ============================ PTX helpers ===================================
__device__ __forceinline__ uint32_t smem_u32(const void* p) {
    uint32_t a;
    asm("{ .reg .u64 t; cvta.to.shared.u64 t, %1; cvt.u32.u64 %0, t; }" : "=r"(a) : "l"(p));
    return a;
}

#define CP_ASYNC16(dst, src) \
    asm volatile("cp.async.cg.shared.global [%0], [%1], 16;" :: "r"(dst), "l"(src) : "memory")
#define CP_COMMIT() asm volatile("cp.async.commit_group;" ::: "memory")
#define CP_WAIT2()  asm volatile("cp.async.wait_group 2;" ::: "memory")
#define CP_WAIT0()  asm volatile("cp.async.wait_group 0;" ::: "memory")

#define LDSM4(r, a) \
    asm volatile("ldmatrix.sync.aligned.m8n8.x4.shared.b16 {%0,%1,%2,%3}, [%4];" \
        : "=r"((r)[0]), "=r"((r)[1]), "=r"((r)[2]), "=r"((r)[3]) : "r"(a))

#define MMAH(d, a, b0, b1) \
    asm volatile("mma.sync.aligned.m16n8k16.row.col.f32.f16.f16.f32 " \
        "{%0,%1,%2,%3}, {%4,%5,%6,%7}, {%8,%9}, {%0,%1,%2,%3};" \
        : "+f"((d)[0]), "+f"((d)[1]), "+f"((d)[2]), "+f"((d)[3]) \
        : "r"((a)[0]), "r"((a)[1]), "r"((a)[2]), "r"((a)[3]), "r"(b0), "r"(b1))

// swizzled addr inside one tile of 128-byte rows (SW128)
__device__ __forceinline__ uint32_t swaddr(uint32_t base, int row, int kb) {
    uint32_t o = (uint32_t)(row * 128 + kb);
    return base + (o ^ ((o >> 3) & 0x70));
}

__device__ __forceinline__ unsigned f2sort(float f) {
    unsigned u = __float_as_uint(f);
    return (u & 0x80000000u) ? ~u : (u | 0x80000000u);
}
__device__ __forceinline__ float sort2f(unsigned u) {
    unsigned fb = (u & 0x80000000u) ? (u ^ 0x80000000u) : ~u;
    return __uint_as_float(fb);
}
__device__ __forceinline__ unsigned h2sort(unsigned hbits) {
    return (hbits & 0x8000u) ? (0xFFFFu & ~hbits) : (hbits | 0x8000u);
}
__device__ __forceinline__ float sort2h(unsigned u) {
    unsigned hb = (u & 0x8000u) ? (u ^ 0x8000u) : (0xFFFFu & ~u);
    __half h = __ushort_as_half((unsigned short)hb);
    return __half2float(h);
}

// =================== prep kernels ===========================================
__global__ void k_split_q(const float4* __restrict__ src) {
    size_t i = (size_t)blockIdx.x * 256 + threadIdx.x;
    float4 v = src[i];
    __half2* dh = (__half2*)g_qh;
    dh[2 * i]     = __floats2half2_rn(v.x * SCALE, v.y * SCALE);
    dh[2 * i + 1] = __floats2half2_rn(v.z * SCALE, v.w * SCALE);
}

__global__ void k_prep_k(const float* __restrict__ keys) {
    __shared__ float t[32][33];
    int b = blockIdx.z, d0 = blockIdx.x * 32, k0 = blockIdx.y * 32;
    int tx = threadIdx.x, ty = threadIdx.y;
#pragma unroll
    for (int j = 0; j < 4; j++) {
        int kk = k0 + ty + 8 * j;
        float f = keys[((size_t)b * LK + kk) * D_ + d0 + tx];
        t[ty + 8 * j][tx] = f;
        g_kh[((size_t)b * LK + kk) * D_ + d0 + tx] = __float2half_rn(f);
    }
    __syncthreads();
#pragma unroll
    for (int j = 0; j < 4; j++)
        g_kt[((size_t)b * D_ + d0 + ty + 8 * j) * LK + k0 + tx] =
            __float2half_rn(t[tx][ty + 8 * j]);
}

__global__ void k_prep_v(const float* __restrict__ v) {
    __shared__ float t[32][33];
    __shared__ float ps[8][33];
    int b = blockIdx.z, d0 = blockIdx.x * 32, kblk = blockIdx.y;
    int k0 = kblk * 32;
    int tx = threadIdx.x, ty = threadIdx.y;
#pragma unroll
    for (int j = 0; j < 4; j++)
        t[ty + 8 * j][tx] = v[((size_t)b * LK + k0 + ty + 8 * j) * D_ + d0 + tx];
    __syncthreads();
#pragma unroll
    for (int j = 0; j < 4; j++)
        g_vth[((size_t)b * D_ + d0 + ty + 8 * j) * LK + k0 + tx] =
            __float2half_rn(t[tx][ty + 8 * j]);
    float s = 0.f;
#pragma unroll
    for (int j = 0; j < 4; j++) s += t[ty * 4 + j][tx];
    ps[ty][tx] = s;
    __syncthreads();
    if (ty == 0) {
        double acc = 0.0;
#pragma unroll
        for (int j = 0; j < 8; j++) acc += (double)ps[j][tx];
        g_meanpart[((size_t)b * 128 + kblk) * D_ + d0 + tx] = acc;
    }
}

// =================== K_reduce: fp16 keys, 2-pass radix, register-resident ===
__global__ void k_kreduce() {
    __shared__ unsigned hist[256];
    __shared__ unsigned s_pref, s_need;
    __shared__ double red[256];
    int bd = blockIdx.x;
    int tid = threadIdx.x;
    const __half2* kp = (const __half2*)(g_kt + (size_t)bd * LK);
    unsigned uv[16];

    if (tid == 0) { s_pref = 0; s_need = LSEL; }
    hist[tid] = 0;
    __syncthreads();

    // load + convert to sortable (registers) + pass-1 histogram
#pragma unroll
    for (int j = 0; j < 8; j++) {
        __half2 h2 = kp[tid + 256 * j];
        unsigned bits = *(const unsigned*)&h2;
        uv[2 * j]     = h2sort(bits & 0xFFFFu);
        uv[2 * j + 1] = h2sort(bits >> 16);
        atomicAdd(&hist[uv[2 * j] >> 8], 1);
        atomicAdd(&hist[uv[2 * j + 1] >> 8], 1);
    }
    __syncthreads();
    if (tid == 0) {
        unsigned cum = 0, need = LSEL;
        for (int bin = 255; bin >= 0; bin--) {
            unsigned c = hist[bin];
            if (cum + c >= need) { s_need = need - cum; s_pref = (unsigned)bin; break; }
            cum += c;
        }
    }
    __syncthreads();
    unsigned pref = s_pref;
    hist[tid] = 0;
    __syncthreads();
    // pass 2: low byte within pref (from registers)
#pragma unroll
    for (int j = 0; j < 16; j++)
        if ((uv[j] >> 8) == pref) atomicAdd(&hist[uv[j] & 255], 1);
    __syncthreads();
    if (tid == 0) {
        unsigned cum = 0, need = s_need;
        for (int bin = 255; bin >= 0; bin--) {
            unsigned c = hist[bin];
            if (cum + c >= need) { s_need = need - cum; s_pref = (pref << 8) | (unsigned)bin; break; }
            cum += c;
        }
    }
    __syncthreads();
    unsigned tu = s_pref, need = s_need;
    double acc = 0.0;
#pragma unroll
    for (int j = 0; j < 16; j++)
        if (uv[j] > tu) acc += (double)sort2h(uv[j]);
    red[tid] = acc;
    __syncthreads();
    for (int t = 128; t > 0; t >>= 1) {
        if (tid < t) red[tid] += red[tid + t];
        __syncthreads();
    }
    if (tid == 0)
        g_kreduce[bd] = (float)((red[0] + (double)need * (double)sort2h(tu)) / (double)LSEL);
}

__global__ void k_meanfin() {
    int b = blockIdx.x, d = threadIdx.x;
    double s = 0.0;
    for (int j = 0; j < 128; j++) s += g_meanpart[((size_t)b * 128 + j) * D_ + d];
    g_meanvals[b * D_ + d] = (float)(s / (double)LK);
}

// =================== sqk = Q . K_reduce (fp64, exact path) ===================
__global__ void k_sqk(const float* __restrict__ queries) {
    __shared__ float kr[D_];
    int warp = threadIdx.x >> 5, lane = threadIdx.x & 31;
    int qflat = blockIdx.x * 8 + warp;
    int b = qflat >> 12;
    for (int i = threadIdx.x; i < D_; i += 256) kr[i] = g_kreduce[b * D_ + i];
    __syncthreads();
    const float* qp = queries + (size_t)qflat * D_;
    double acc = 0.0;
#pragma unroll
    for (int j = 0; j < 16; j++) {
        int d = lane + 32 * j;
        acc += (double)qp[d] * (double)kr[d];
    }
    for (int off = 16; off; off >>= 1) acc += __shfl_down_sync(0xffffffffu, acc, off);
    if (lane == 0) g_sqk[qflat] = (float)acc;
}

// =================== threshold + compaction (fused, exact 32-bit radix) =====
__global__ void k_thresh() {
    __shared__ unsigned su[4096];
    __shared__ unsigned hist[256];
    __shared__ unsigned s_pref, s_need;
    int b = blockIdx.x, tid = threadIdx.x;
    if (tid == 0) { s_pref = 0; s_need = LSEL; g_selcnt[b] = 0; }
    __syncthreads();
    for (int i = tid; i < 4096; i += 256) su[i] = f2sort(g_sqk[b * LQ + i]);
    __syncthreads();
    unsigned pref = 0, need = LSEL;
    for (int pass = 3; pass >= 0; pass--) {
        hist[tid] = 0;
        __syncthreads();
        for (int i = tid; i < 4096; i += 256) {
            unsigned u = su[i];
            unsigned hi = (pass == 3) ? 0u : (u >> ((pass + 1) * 8));
            if (hi == pref) atomicAdd(&hist[(u >> (pass * 8)) & 255], 1);
        }
        __syncthreads();
        if (tid == 0) {
            unsigned cum = 0;
            for (int bin = 255; bin >= 0; bin--) {
                unsigned c = hist[bin];
                if (cum + c >= need) {
                    s_need = need - cum;
                    s_pref = (pref << 8) | (unsigned)bin;
                    break;
                }
                cum += c;
            }
        }
        __syncthreads();
        pref = s_pref; need = s_need;
        __syncthreads();
    }
    unsigned tu = s_pref;
    if (tid == 0) g_thresh[b] = sort2f(tu);
    for (int i = tid; i < 4096; i += 256) {
        if (su[i] >= tu) {
            int pos = atomicAdd(&g_selcnt[b], 1);
            if (pos < LSEL) g_selidx[b * LSEL + pos] = i;
        }
    }
}

__global__ void k_fill(float* __restrict__ out) {
    int r = blockIdx.x, b = r >> 12;
    if (g_sqk[r] < g_thresh[b]) {
        const float4* mv = (const float4*)(g_meanvals + b * D_);
        float4* op = (float4*)(out + (size_t)r * D_);
        op[threadIdx.x] = mv[threadIdx.x];
    }
}

// =================== 1-pass fp16 tile compute (128x128, warp 32x64) =========
__device__ __forceinline__ void gemm_stage1(uint32_t st, int wm, int wn, int lane,
                                            float d[2][8][4]) {
    int rA = wm * 32 + (lane & 15);
    int kA = (lane >> 4) * 16;
    int rB = wn * 64 + (lane & 7) + ((lane >> 4) << 3);
    int kB = ((lane >> 3) & 1) * 16;
#pragma unroll
    for (int t = 0; t < 4; t++) {
        uint32_t a0[4], a1[4];
        LDSM4(a0, swaddr(st, rA, t * 32 + kA));
        LDSM4(a1, swaddr(st, rA + 16, t * 32 + kA));
#pragma unroll
        for (int p = 0; p < 4; p++) {
            uint32_t bh[4];
            LDSM4(bh, swaddr(st + 16384, rB + p * 16, t * 32 + kB));
            MMAH(d[0][2 * p],     a0, bh[0], bh[1]);
            MMAH(d[0][2 * p + 1], a0, bh[2], bh[3]);
            MMAH(d[1][2 * p],     a1, bh[0], bh[1]);
            MMAH(d[1][2 * p + 1], a1, bh[2], bh[3]);
        }
    }
}

#define SMEM_DYN (3 * 32768)

// =================== GEMM 1: E = exp(Qsel@K^T), row-sum partials ============
__global__ void __launch_bounds__(256, 2) k_gemm_qk() {
    extern __shared__ char dsm[];
    __shared__ int srow[128];
    __shared__ float zsh[2][128];
    uint32_t sb = smem_u32(dsm);
    int tid = threadIdx.x;
    int b = blockIdx.z, m0 = blockIdx.y * 128, n0 = blockIdx.x * 128;

    if (tid < 128) {
        int m = m0 + tid;
        srow[tid] = g_selidx[b * LSEL + (m < LSEL ? m : 0)];
    }
    __syncthreads();

    const __half* baseA = g_qh + (size_t)b * LQ * D_;
    const __half* baseB = g_kh + ((size_t)b * LK + n0) * D_;

#define QK_FILL(s, k) do {                                                     \
    uint32_t st_ = sb + (s) * 32768;                                           \
    int k0_ = (k) * 64;                                                        \
    for (int idx = tid; idx < 2048; idx += 256) {                              \
        int tile_ = idx >> 10, r_ = (idx >> 3) & 127, seg_ = idx & 7;          \
        const __half* src_ = (tile_ == 0)                                      \
            ? baseA + (size_t)srow[r_] * D_ + k0_ + seg_ * 8                   \
            : baseB + (size_t)r_ * D_ + k0_ + seg_ * 8;                        \
        CP_ASYNC16(swaddr(st_ + tile_ * 16384, r_, seg_ * 16), src_);          \
    } CP_COMMIT(); } while (0)

    QK_FILL(0, 0); QK_FILL(1, 1); QK_FILL(2, 2);

    int lane = tid & 31, w = tid >> 5, wm = w >> 1, wn = w & 1;
    float d[2][8][4] = {};

    for (int k = 0; k < 8; k++) {
        int s = k % 3;
        if (k == 7) { CP_WAIT0(); } else { CP_WAIT2(); }
        __syncthreads();
        gemm_stage1(sb + s * 32768, wm, wn, lane, d);
        __syncthreads();
        if (k + 3 < 8) QK_FILL(s, k + 3);
    }

    float rs[2][2] = {};
#pragma unroll
    for (int i = 0; i < 2; i++)
#pragma unroll
        for (int j = 0; j < 8; j++) {
            d[i][j][0] = __expf(d[i][j][0]);
            d[i][j][1] = __expf(d[i][j][1]);
            d[i][j][2] = __expf(d[i][j][2]);
            d[i][j][3] = __expf(d[i][j][3]);
            rs[i][0] += d[i][j][0] + d[i][j][1];
            rs[i][1] += d[i][j][2] + d[i][j][3];
        }
#pragma unroll
    for (int i = 0; i < 2; i++)
#pragma unroll
        for (int h = 0; h < 2; h++) {
            rs[i][h] += __shfl_xor_sync(0xffffffffu, rs[i][h], 1);
            rs[i][h] += __shfl_xor_sync(0xffffffffu, rs[i][h], 2);
        }
    if ((lane & 3) == 0) {
        int rl = wm * 32 + (lane >> 2);
        zsh[wn][rl]      = rs[0][0];
        zsh[wn][rl + 8]  = rs[0][1];
        zsh[wn][rl + 16] = rs[1][0];
        zsh[wn][rl + 24] = rs[1][1];
    }

    int mBase = m0 + wm * 32, nBase = n0 + wn * 64;
#pragma unroll
    for (int i = 0; i < 2; i++) {
        int r = mBase + i * 16 + (lane >> 2);
#pragma unroll
        for (int j = 0; j < 8; j++) {
            int c = nBase + j * 8 + (lane & 3) * 2;
            if (r < LSEL)
                *(__half2*)(g_E + ((size_t)b * MPAD + r) * LK + c) =
                    __floats2half2_rn(d[i][j][0], d[i][j][1]);
            if (r + 8 < LSEL)
                *(__half2*)(g_E + ((size_t)b * MPAD + r + 8) * LK + c) =
                    __floats2half2_rn(d[i][j][2], d[i][j][3]);
        }
    }
    __syncthreads();
    if (tid < 128) {
        float z = zsh[0][tid] + zsh[1][tid];
        g_Zpart[(size_t)(b * MPAD + m0 + tid) * 32 + blockIdx.x] = z;
    }
}

// =================== GEMM 2: O = (E @ V)/Z, scatter, Z folded ===============
__global__ void __launch_bounds__(256, 2) k_gemm_pv(float* __restrict__ out) {
    extern __shared__ char dsm[];
    __shared__ int srow[128];
    __shared__ float zrow[128];
    uint32_t sb = smem_u32(dsm);
    int tid = threadIdx.x;
    int b = blockIdx.z, m0 = blockIdx.y * 128, n0 = blockIdx.x * 128;

    if (tid < 128) {
        int m = m0 + tid;
        srow[tid] = g_selidx[b * LSEL + (m < LSEL ? m : 0)];
    }
    __syncthreads();

    const __half* baseA = g_E + ((size_t)b * MPAD + m0) * LK;
    const __half* baseB = g_vth + ((size_t)b * D_ + n0) * LK;

#define PV_FILL(s, k) do {                                                     \
    uint32_t st_ = sb + (s) * 32768;                                           \
    int k0_ = (k) * 64;                                                        \
    for (int idx = tid; idx < 2048; idx += 256) {                              \
        int tile_ = idx >> 10, r_ = (idx >> 3) & 127, seg_ = idx & 7;          \
        const __half* src_ = (tile_ == 0)                                      \
            ? baseA + (size_t)r_ * LK + k0_ + seg_ * 8                         \
            : baseB + (size_t)r_ * LK + k0_ + seg_ * 8;                        \
        CP_ASYNC16(swaddr(st_ + tile_ * 16384, r_, seg_ * 16), src_);          \
    } CP_COMMIT(); } while (0)

    PV_FILL(0, 0); PV_FILL(1, 1); PV_FILL(2, 2);

    int lane = tid & 31, w = tid >> 5, wm = w >> 1, wn = w & 1;
    float d[2][8][4] = {};

    for (int k = 0; k < 64; k++) {
        int s = k % 3;
        if (k == 63) { CP_WAIT0(); } else { CP_WAIT2(); }
        __syncthreads();
        gemm_stage1(sb + s * 32768, wm, wn, lane, d);
        __syncthreads();
        if (k + 3 < 64) PV_FILL(s, k + 3);
    }

    // fold Z reduction: sum 32 per-tile partials for this CTA's 128 rows
    if (tid < 128) {
        const float* p = g_Zpart + (size_t)(b * MPAD + m0 + tid) * 32;
        float s = 0.f;
#pragma unroll
        for (int i = 0; i < 32; i++) s += p[i];
        zrow[tid] = s;
    }
    __syncthreads();

    int nBase = n0 + wn * 64;
#pragma unroll
    for (int i = 0; i < 2; i++) {
        int lr = wm * 32 + i * 16 + (lane >> 2);
        int m = m0 + lr;
        float zi0 = 1.0f / zrow[lr];
        float zi1 = 1.0f / zrow[lr + 8];
        int q0 = srow[lr], q1 = srow[lr + 8];
#pragma unroll
        for (int j = 0; j < 8; j++) {
            int c = nBase + j * 8 + (lane & 3) * 2;
            if (m < LSEL)
                *(float2*)(out + ((size_t)b * LQ + q0) * D_ + c) =
                    float2{d[i][j][0] * zi0, d[i][j][1] * zi0};
            if (m + 8 < LSEL)
                *(float2*)(out + ((size_t)b * LQ + q1) * D_ + c) =
                    float2{d[i][j][2] * zi1, d[i][j][3] * zi1};
        }
    }
}

// =================== launch ==================================================
extern "C" void kernel_launch(void* const* d_in, const int* in_sizes, int n_in,
                              void* d_out, int out_size) {
    const float* q = (const float*)d_in[0];
    const float* k = (const float*)d_in[1];
    const float* v = (const float*)d_in[2];
    float* out = (float*)d_out;

    cudaFuncSetAttribute(k_gemm_qk, cudaFuncAttributeMaxDynamicSharedMemorySize, SMEM_DYN);
    cudaFuncSetAttribute(k_gemm_pv, cudaFuncAttributeMaxDynamicSharedMemorySize, SMEM_DYN);

    k_split_q<<<16384, 256>>>((const float4*)q);
    k_prep_k<<<dim3(16, 128, 8), dim3(32, 8)>>>(k);
    k_prep_v<<<dim3(16, 128, 8), dim3(32, 8)>>>(v);

    k_kreduce<<<B_ * D_, 256>>>();
    k_meanfin<<<B_, 512>>>();
    k_sqk<<<B_ * LQ / 8, 256>>>(q);
    k_thresh<<<B_, 256>>>();
    k_fill<<<B_ * LQ, 128>>>(out);

    dim3 g1(LK / 128, (LSEL + 127) / 128, B_);   // 32 x 22 x 8
    k_gemm_qk<<<g1, 256, SMEM_DYN>>>();

    dim3 g2(D_ / 128, (LSEL + 127) / 128, B_);   // 4 x 22 x 8
    k_gemm_pv<<<g2, 256, SMEM_DYN>>>(out);
}

// round 13
// speedup vs baseline: 1.2523x; 1.0374x over previous
#include <cuda_runtime.h>
#include <cuda_fp16.h>
#include <cstdint>

#define B_    8
#define LQ    4096
#define LK    4096
#define D_    512
#define LSEL  2744
#define MPAD  2816
#define SCALE 0.04419417382415922f   // 1/sqrt(512)

// ============================ device scratch ================================
__device__ __half g_qh[B_ * LQ * D_];           // Q*SCALE fp16
__device__ __half g_kh[B_ * LK * D_];           // K fp16
__device__ __half g_vth[B_ * D_ * LK];          // V^T fp16 [b][d][k]
__device__ __half g_E[(size_t)B_ * MPAD * LK];  // exp(S) fp16 [b][m][k]
__device__ __half g_kt[(size_t)B_ * D_ * LK];   // K^T fp16 [b][d][k]
__device__ float  g_Zpart[B_ * MPAD * 32];
__device__ float  g_kreduce[B_ * D_];
__device__ double g_meanpart[B_ * 128 * D_];
__device__ float  g_meanvals[B_ * D_];
__device__ float  g_sqk[B_ * LQ];
__device__ float  g_thresh[B_];
__device__ int    g_selidx[B_ * LSEL];
__device__ int    g_selcnt[B_];

// ============================ PTX helpers ===================================
__device__ __forceinline__ uint32_t smem_u32(const void* p) {
    uint32_t a;
    asm("{ .reg .u64 t; cvta.to.shared.u64 t, %1; cvt.u32.u64 %0, t; }" : "=r"(a) : "l"(p));
    return a;
}

#define CP_ASYNC16(dst, src) \
    asm volatile("cp.async.cg.shared.global [%0], [%1], 16;" :: "r"(dst), "l"(src) : "memory")
#define CP_COMMIT() asm volatile("cp.async.commit_group;" ::: "memory")
#define CP_WAIT2()  asm volatile("cp.async.wait_group 2;" ::: "memory")
#define CP_WAIT0()  asm volatile("cp.async.wait_group 0;" ::: "memory")

#define LDSM4(r, a) \
    asm volatile("ldmatrix.sync.aligned.m8n8.x4.shared.b16 {%0,%1,%2,%3}, [%4];" \
        : "=r"((r)[0]), "=r"((r)[1]), "=r"((r)[2]), "=r"((r)[3]) : "r"(a))

#define MMAH(d, a, b0, b1) \
    asm volatile("mma.sync.aligned.m16n8k16.row.col.f32.f16.f16.f32 " \
        "{%0,%1,%2,%3}, {%4,%5,%6,%7}, {%8,%9}, {%0,%1,%2,%3};" \
        : "+f"((d)[0]), "+f"((d)[1]), "+f"((d)[2]), "+f"((d)[3]) \
        : "r"((a)[0]), "r"((a)[1]), "r"((a)[2]), "r"((a)[3]), "r"(b0), "r"(b1))

// swizzled addr inside one tile of 128-byte rows (SW128)
__device__ __forceinline__ uint32_t swaddr(uint32_t base, int row, int kb) {
    uint32_t o = (uint32_t)(row * 128 + kb);
    return base + (o ^ ((o >> 3) & 0x70));
}

__device__ __forceinline__ unsigned f2sort(float f) {
    unsigned u = __float_as_uint(f);
    return (u & 0x80000000u) ? ~u : (u | 0x80000000u);
}
__device__ __forceinline__ float sort2f(unsigned u) {
    unsigned fb = (u & 0x80000000u) ? (u ^ 0x80000000u) : ~u;
    return __uint_as_float(fb);
}
__device__ __forceinline__ unsigned h2sort(unsigned hbits) {
    return (hbits & 0x8000u) ? (0xFFFFu & ~hbits) : (hbits | 0x8000u);
}
__device__ __forceinline__ float sort2h(unsigned u) {
    unsigned hb = (u & 0x8000u) ? (u ^ 0x8000u) : (0xFFFFu & ~u);
    __half h = __ushort_as_half((unsigned short)hb);
    return __half2float(h);
}

// =================== prep kernels ===========================================
__global__ void k_split_q(const float4* __restrict__ src) {
    size_t i = (size_t)blockIdx.x * 256 + threadIdx.x;
    float4 v = src[i];
    __half2* dh = (__half2*)g_qh;
    dh[2 * i]     = __floats2half2_rn(v.x * SCALE, v.y * SCALE);
    dh[2 * i + 1] = __floats2half2_rn(v.z * SCALE, v.w * SCALE);
}

__global__ void k_prep_k(const float* __restrict__ keys) {
    __shared__ float t[32][33];
    int b = blockIdx.z, d0 = blockIdx.x * 32, k0 = blockIdx.y * 32;
    int tx = threadIdx.x, ty = threadIdx.y;
#pragma unroll
    for (int j = 0; j < 4; j++) {
        int kk = k0 + ty + 8 * j;
        float f = keys[((size_t)b * LK + kk) * D_ + d0 + tx];
        t[ty + 8 * j][tx] = f;
        g_kh[((size_t)b * LK + kk) * D_ + d0 + tx] = __float2half_rn(f);
    }
    __syncthreads();
#pragma unroll
    for (int j = 0; j < 4; j++)
        g_kt[((size_t)b * D_ + d0 + ty + 8 * j) * LK + k0 + tx] =
            __float2half_rn(t[tx][ty + 8 * j]);
}

__global__ void k_prep_v(const float* __restrict__ v) {
    __shared__ float t[32][33];
    __shared__ float ps[8][33];
    int b = blockIdx.z, d0 = blockIdx.x * 32, kblk = blockIdx.y;
    int k0 = kblk * 32;
    int tx = threadIdx.x, ty = threadIdx.y;
#pragma unroll
    for (int j = 0; j < 4; j++)
        t[ty + 8 * j][tx] = v[((size_t)b * LK + k0 + ty + 8 * j) * D_ + d0 + tx];
    __syncthreads();
#pragma unroll
    for (int j = 0; j < 4; j++)
        g_vth[((size_t)b * D_ + d0 + ty + 8 * j) * LK + k0 + tx] =
            __float2half_rn(t[tx][ty + 8 * j]);
    float s = 0.f;
#pragma unroll
    for (int j = 0; j < 4; j++) s += t[ty * 4 + j][tx];
    ps[ty][tx] = s;
    __syncthreads();
    if (ty == 0) {
        double acc = 0.0;
#pragma unroll
        for (int j = 0; j < 8; j++) acc += (double)ps[j][tx];
        g_meanpart[((size_t)b * 128 + kblk) * D_ + d0 + tx] = acc;
    }
}

// =================== K_reduce: fp16 keys, 2-pass radix (R11 version) ========
__global__ void k_kreduce() {
    __shared__ unsigned short su[4096];
    __shared__ unsigned hist[256];
    __shared__ unsigned s_pref, s_need;
    __shared__ double red[256];
    int bd = blockIdx.x;
    int tid = threadIdx.x;
    const __half2* kp = (const __half2*)(g_kt + (size_t)bd * LK);

    if (tid == 0) { s_pref = 0; s_need = LSEL; }
    hist[tid] = 0;
    __syncthreads();

#pragma unroll
    for (int j = 0; j < 8; j++) {
        int i = tid + 256 * j;
        __half2 h2 = kp[i];
        unsigned bits = *(const unsigned*)&h2;
        unsigned u0 = h2sort(bits & 0xFFFFu);
        unsigned u1 = h2sort(bits >> 16);
        su[2 * i]     = (unsigned short)u0;
        su[2 * i + 1] = (unsigned short)u1;
        atomicAdd(&hist[u0 >> 8], 1);
        atomicAdd(&hist[u1 >> 8], 1);
    }
    __syncthreads();
    if (tid == 0) {
        unsigned cum = 0, need = LSEL;
        for (int bin = 255; bin >= 0; bin--) {
            unsigned c = hist[bin];
            if (cum + c >= need) { s_need = need - cum; s_pref = (unsigned)bin; break; }
            cum += c;
        }
    }
    __syncthreads();
    unsigned pref = s_pref;
    hist[tid] = 0;
    __syncthreads();
    for (int i = tid; i < 4096; i += 256) {
        unsigned u = su[i];
        if ((u >> 8) == pref) atomicAdd(&hist[u & 255], 1);
    }
    __syncthreads();
    if (tid == 0) {
        unsigned cum = 0, need = s_need;
        for (int bin = 255; bin >= 0; bin--) {
            unsigned c = hist[bin];
            if (cum + c >= need) { s_need = need - cum; s_pref = (pref << 8) | (unsigned)bin; break; }
            cum += c;
        }
    }
    __syncthreads();
    unsigned tu = s_pref, need = s_need;
    double acc = 0.0;
    for (int i = tid; i < 4096; i += 256) {
        unsigned u = su[i];
        if (u > tu) acc += (double)sort2h(u);
    }
    red[tid] = acc;
    __syncthreads();
    for (int t = 128; t > 0; t >>= 1) {
        if (tid < t) red[tid] += red[tid + t];
        __syncthreads();
    }
    if (tid == 0)
        g_kreduce[bd] = (float)((red[0] + (double)need * (double)sort2h(tu)) / (double)LSEL);
}

__global__ void k_meanfin() {
    int b = blockIdx.x, d = threadIdx.x;
    double s = 0.0;
    for (int j = 0; j < 128; j++) s += g_meanpart[((size_t)b * 128 + j) * D_ + d];
    g_meanvals[b * D_ + d] = (float)(s / (double)LK);
}

// =================== sqk = Q . K_reduce (fp64, exact path) ===================
__global__ void k_sqk(const float* __restrict__ queries) {
    __shared__ float kr[D_];
    int warp = threadIdx.x >> 5, lane = threadIdx.x & 31;
    int qflat = blockIdx.x * 8 + warp;
    int b = qflat >> 12;
    for (int i = threadIdx.x; i < D_; i += 256) kr[i] = g_kreduce[b * D_ + i];
    __syncthreads();
    const float* qp = queries + (size_t)qflat * D_;
    double acc = 0.0;
#pragma unroll
    for (int j = 0; j < 16; j++) {
        int d = lane + 32 * j;
        acc += (double)qp[d] * (double)kr[d];
    }
    for (int off = 16; off; off >>= 1) acc += __shfl_down_sync(0xffffffffu, acc, off);
    if (lane == 0) g_sqk[qflat] = (float)acc;
}

// =================== threshold + compaction (fused, exact 32-bit radix) =====
__global__ void k_thresh() {
    __shared__ unsigned su[4096];
    __shared__ unsigned hist[256];
    __shared__ unsigned s_pref, s_need;
    int b = blockIdx.x, tid = threadIdx.x;
    if (tid == 0) { s_pref = 0; s_need = LSEL; g_selcnt[b] = 0; }
    __syncthreads();
    for (int i = tid; i < 4096; i += 256) su[i] = f2sort(g_sqk[b * LQ + i]);
    __syncthreads();
    unsigned pref = 0, need = LSEL;
    for (int pass = 3; pass >= 0; pass--) {
        hist[tid] = 0;
        __syncthreads();
        for (int i = tid; i < 4096; i += 256) {
            unsigned u = su[i];
            unsigned hi = (pass == 3) ? 0u : (u >> ((pass + 1) * 8));
            if (hi == pref) atomicAdd(&hist[(u >> (pass * 8)) & 255], 1);
        }
        __syncthreads();
        if (tid == 0) {
            unsigned cum = 0;
            for (int bin = 255; bin >= 0; bin--) {
                unsigned c = hist[bin];
                if (cum + c >= need) {
                    s_need = need - cum;
                    s_pref = (pref << 8) | (unsigned)bin;
                    break;
                }
                cum += c;
            }
        }
        __syncthreads();
        pref = s_pref; need = s_need;
        __syncthreads();
    }
    unsigned tu = s_pref;
    if (tid == 0) g_thresh[b] = sort2f(tu);
    for (int i = tid; i < 4096; i += 256) {
        if (su[i] >= tu) {
            int pos = atomicAdd(&g_selcnt[b], 1);
            if (pos < LSEL) g_selidx[b * LSEL + pos] = i;
        }
    }
}

__global__ void k_fill(float* __restrict__ out) {
    int r = blockIdx.x, b = r >> 12;
    if (g_sqk[r] < g_thresh[b]) {
        const float4* mv = (const float4*)(g_meanvals + b * D_);
        float4* op = (float4*)(out + (size_t)r * D_);
        op[threadIdx.x] = mv[threadIdx.x];
    }
}

// =================== 1-pass fp16 tile compute (128x128, warp 32x64) =========
__device__ __forceinline__ void gemm_stage1(uint32_t st, int wm, int wn, int lane,
                                            float d[2][8][4]) {
    int rA = wm * 32 + (lane & 15);
    int kA = (lane >> 4) * 16;
    int rB = wn * 64 + (lane & 7) + ((lane >> 4) << 3);
    int kB = ((lane >> 3) & 1) * 16;
#pragma unroll
    for (int t = 0; t < 4; t++) {
        uint32_t a0[4], a1[4];
        LDSM4(a0, swaddr(st, rA, t * 32 + kA));
        LDSM4(a1, swaddr(st, rA + 16, t * 32 + kA));
#pragma unroll
        for (int p = 0; p < 4; p++) {
            uint32_t bh[4];
            LDSM4(bh, swaddr(st + 16384, rB + p * 16, t * 32 + kB));
            MMAH(d[0][2 * p],     a0, bh[0], bh[1]);
            MMAH(d[0][2 * p + 1], a0, bh[2], bh[3]);
            MMAH(d[1][2 * p],     a1, bh[0], bh[1]);
            MMAH(d[1][2 * p + 1], a1, bh[2], bh[3]);
        }
    }
}

#define SMEM_DYN (3 * 32768)

// =================== GEMM 1: E = exp(Qsel@K^T), row-sum partials ============
__global__ void __launch_bounds__(256, 2) k_gemm_qk() {
    extern __shared__ char dsm[];
    __shared__ int srow[128];
    __shared__ float zsh[2][128];
    uint32_t sb = smem_u32(dsm);
    int tid = threadIdx.x;
    int b = blockIdx.z, m0 = blockIdx.y * 128, n0 = blockIdx.x * 128;

    if (tid < 128) {
        int m = m0 + tid;
        srow[tid] = g_selidx[b * LSEL + (m < LSEL ? m : 0)];
    }
    __syncthreads();

    const __half* baseA = g_qh + (size_t)b * LQ * D_;
    const __half* baseB = g_kh + ((size_t)b * LK + n0) * D_;

#define QK_FILL(s, k) do {                                                     \
    uint32_t st_ = sb + (s) * 32768;                                           \
    int k0_ = (k) * 64;                                                        \
    for (int idx = tid; idx < 2048; idx += 256) {                              \
        int tile_ = idx >> 10, r_ = (idx >> 3) & 127, seg_ = idx & 7;          \
        const __half* src_ = (tile_ == 0)                                      \
            ? baseA + (size_t)srow[r_] * D_ + k0_ + seg_ * 8                   \
            : baseB + (size_t)r_ * D_ + k0_ + seg_ * 8;                        \
        CP_ASYNC16(swaddr(st_ + tile_ * 16384, r_, seg_ * 16), src_);          \
    } CP_COMMIT(); } while (0)

    QK_FILL(0, 0); QK_FILL(1, 1); QK_FILL(2, 2);

    int lane = tid & 31, w = tid >> 5, wm = w >> 1, wn = w & 1;
    float d[2][8][4] = {};

    for (int k = 0; k < 8; k++) {
        int s = k % 3;
        if (k == 7) { CP_WAIT0(); } else { CP_WAIT2(); }
        __syncthreads();
        gemm_stage1(sb + s * 32768, wm, wn, lane, d);
        __syncthreads();
        if (k + 3 < 8) QK_FILL(s, k + 3);
    }

    float rs[2][2] = {};
#pragma unroll
    for (int i = 0; i < 2; i++)
#pragma unroll
        for (int j = 0; j < 8; j++) {
            d[i][j][0] = __expf(d[i][j][0]);
            d[i][j][1] = __expf(d[i][j][1]);
            d[i][j][2] = __expf(d[i][j][2]);
            d[i][j][3] = __expf(d[i][j][3]);
            rs[i][0] += d[i][j][0] + d[i][j][1];
            rs[i][1] += d[i][j][2] + d[i][j][3];
        }
#pragma unroll
    for (int i = 0; i < 2; i++)
#pragma unroll
        for (int h = 0; h < 2; h++) {
            rs[i][h] += __shfl_xor_sync(0xffffffffu, rs[i][h], 1);
            rs[i][h] += __shfl_xor_sync(0xffffffffu, rs[i][h], 2);
        }
    if ((lane & 3) == 0) {
        int rl = wm * 32 + (lane >> 2);
        zsh[wn][rl]      = rs[0][0];
        zsh[wn][rl + 8]  = rs[0][1];
        zsh[wn][rl + 16] = rs[1][0];
        zsh[wn][rl + 24] = rs[1][1];
    }

    int mBase = m0 + wm * 32, nBase = n0 + wn * 64;
#pragma unroll
    for (int i = 0; i < 2; i++) {
        int r = mBase + i * 16 + (lane >> 2);
#pragma unroll
        for (int j = 0; j < 8; j++) {
            int c = nBase + j * 8 + (lane & 3) * 2;
            if (r < LSEL)
                *(__half2*)(g_E + ((size_t)b * MPAD + r) * LK + c) =
                    __floats2half2_rn(d[i][j][0], d[i][j][1]);
            if (r + 8 < LSEL)
                *(__half2*)(g_E + ((size_t)b * MPAD + r + 8) * LK + c) =
                    __floats2half2_rn(d[i][j][2], d[i][j][3]);
        }
    }
    __syncthreads();
    if (tid < 128) {
        float z = zsh[0][tid] + zsh[1][tid];
        g_Zpart[(size_t)(b * MPAD + m0 + tid) * 32 + blockIdx.x] = z;
    }
}

// =================== GEMM 2: O = (E @ V)/Z, scatter, Z folded ===============
__global__ void __launch_bounds__(256, 2) k_gemm_pv(float* __restrict__ out) {
    extern __shared__ char dsm[];
    __shared__ int srow[128];
    __shared__ float zrow[128];
    uint32_t sb = smem_u32(dsm);
    int tid = threadIdx.x;
    int b = blockIdx.z, m0 = blockIdx.y * 128, n0 = blockIdx.x * 128;

    if (tid < 128) {
        int m = m0 + tid;
        srow[tid] = g_selidx[b * LSEL + (m < LSEL ? m : 0)];
    }
    __syncthreads();

    const __half* baseA = g_E + ((size_t)b * MPAD + m0) * LK;
    const __half* baseB = g_vth + ((size_t)b * D_ + n0) * LK;

#define PV_FILL(s, k) do {                                                     \
    uint32_t st_ = sb + (s) * 32768;                                           \
    int k0_ = (k) * 64;                                                        \
    for (int idx = tid; idx < 2048; idx += 256) {                              \
        int tile_ = idx >> 10, r_ = (idx >> 3) & 127, seg_ = idx & 7;          \
        const __half* src_ = (tile_ == 0)                                      \
            ? baseA + (size_t)r_ * LK + k0_ + seg_ * 8                         \
            : baseB + (size_t)r_ * LK + k0_ + seg_ * 8;                        \
        CP_ASYNC16(swaddr(st_ + tile_ * 16384, r_, seg_ * 16), src_);          \
    } CP_COMMIT(); } while (0)

    PV_FILL(0, 0); PV_FILL(1, 1); PV_FILL(2, 2);

    int lane = tid & 31, w = tid >> 5, wm = w >> 1, wn = w & 1;
    float d[2][8][4] = {};

    for (int k = 0; k < 64; k++) {
        int s = k % 3;
        if (k == 63) { CP_WAIT0(); } else { CP_WAIT2(); }
        __syncthreads();
        gemm_stage1(sb + s * 32768, wm, wn, lane, d);
        __syncthreads();
        if (k + 3 < 64) PV_FILL(s, k + 3);
    }

    if (tid < 128) {
        const float* p = g_Zpart + (size_t)(b * MPAD + m0 + tid) * 32;
        float s = 0.f;
#pragma unroll
        for (int i = 0; i < 32; i++) s += p[i];
        zrow[tid] = s;
    }
    __syncthreads();

    int nBase = n0 + wn * 64;
#pragma unroll
    for (int i = 0; i < 2; i++) {
        int lr = wm * 32 + i * 16 + (lane >> 2);
        int m = m0 + lr;
        float zi0 = 1.0f / zrow[lr];
        float zi1 = 1.0f / zrow[lr + 8];
        int q0 = srow[lr], q1 = srow[lr + 8];
#pragma unroll
        for (int j = 0; j < 8; j++) {
            int c = nBase + j * 8 + (lane & 3) * 2;
            if (m < LSEL)
                *(float2*)(out + ((size_t)b * LQ + q0) * D_ + c) =
                    float2{d[i][j][0] * zi0, d[i][j][1] * zi0};
            if (m + 8 < LSEL)
                *(float2*)(out + ((size_t)b * LQ + q1) * D_ + c) =
                    float2{d[i][j][2] * zi1, d[i][j][3] * zi1};
        }
    }
}

// =================== streams/events (created at static init, pre-capture) ==
static cudaStream_t hx_sb = nullptr;
static cudaEvent_t hx_ev0, hx_evQ, hx_evV, hx_evB, hx_evJ;
static void hx_init() {
    if (!hx_sb) {
        cudaStreamCreateWithFlags(&hx_sb, cudaStreamNonBlocking);
        cudaEventCreateWithFlags(&hx_ev0, cudaEventDisableTiming);
        cudaEventCreateWithFlags(&hx_evQ, cudaEventDisableTiming);
        cudaEventCreateWithFlags(&hx_evV, cudaEventDisableTiming);
        cudaEventCreateWithFlags(&hx_evB, cudaEventDisableTiming);
        cudaEventCreateWithFlags(&hx_evJ, cudaEventDisableTiming);
    }
}
static struct HxInit { HxInit() { hx_init(); } } hx_init_obj;

// =================== launch ==================================================
extern "C" void kernel_launch(void* const* d_in, const int* in_sizes, int n_in,
                              void* d_out, int out_size) {
    const float* q = (const float*)d_in[0];
    const float* k = (const float*)d_in[1];
    const float* v = (const float*)d_in[2];
    float* out = (float*)d_out;

    hx_init();
    cudaFuncSetAttribute(k_gemm_qk, cudaFuncAttributeMaxDynamicSharedMemorySize, SMEM_DYN);
    cudaFuncSetAttribute(k_gemm_pv, cudaFuncAttributeMaxDynamicSharedMemorySize, SMEM_DYN);

    // fork side stream
    cudaEventRecord(hx_ev0, 0);
    cudaStreamWaitEvent(hx_sb, hx_ev0, 0);

    // side: Q split, V prep, means — off the selection critical path
    k_split_q<<<16384, 256, 0, hx_sb>>>((const float4*)q);
    cudaEventRecord(hx_evQ, hx_sb);
    k_prep_v<<<dim3(16, 128, 8), dim3(32, 8), 0, hx_sb>>>(v);
    k_meanfin<<<B_, 512, 0, hx_sb>>>();
    cudaEventRecord(hx_evV, hx_sb);

    // main: selection critical path
    k_prep_k<<<dim3(16, 128, 8), dim3(32, 8)>>>(k);
    k_kreduce<<<B_ * D_, 256>>>();
    k_sqk<<<B_ * LQ / 8, 256>>>(q);
    k_thresh<<<B_, 256>>>();
    cudaEventRecord(hx_evB, 0);

    // side: fill unselected rows (needs thresh + meanvals); overlaps QK/PV
    cudaStreamWaitEvent(hx_sb, hx_evB, 0);
    k_fill<<<B_ * LQ, 128, 0, hx_sb>>>(out);
    cudaEventRecord(hx_evJ, hx_sb);

    // main: QK (needs split_q + selection)
    cudaStreamWaitEvent(0, hx_evQ, 0);
    dim3 g1(LK / 128, (LSEL + 127) / 128, B_);   // 32 x 22 x 8
    k_gemm_qk<<<g1, 256, SMEM_DYN>>>();

    // main: PV (needs E/Zpart + vth); fill writes disjoint rows of out
    cudaStreamWaitEvent(0, hx_evV, 0);
    dim3 g2(D_ / 128, (LSEL + 127) / 128, B_);   // 4 x 22 x 8
    k_gemm_pv<<<g2, 256, SMEM_DYN>>>(out);

    // join side stream before the graph's end
    cudaStreamWaitEvent(0, hx_evJ, 0);
}